// round 1
// baseline (speedup 1.0000x reference)
#include <cuda_runtime.h>
#include <cfloat>
#include <math.h>

// Problem constants
#define NROWS 65536
#define KNN   15

// Scratch (device globals — no allocations allowed)
__device__ float g_h1[NROWS * 512];   // layer1 output
__device__ float g_h2[NROWS * 256];   // layer2 output
__device__ float g_z [NROWS * 128];   // layer3 output (z)
__device__ float g_zz[NROWS];         // ||z||^2 per row
__device__ float g_d2[NROWS * 256];   // d2 - zz  (250 real protos, padded to 256)
__device__ float g_wd[128 * 256];     // -2 * protos^T, padded cols zeroed
__device__ float g_bd[256];           // ||proto||^2 per col, pad = 1e30

// ---------------------------------------------------------------------------
// Fused GEMM: Out[M,N] = epilogue( X[M,K] @ W[K,N] + b )
// epilogue: optional LayerNorm(gamma,beta) over N, optional ReLU,
//           optional per-row squared-norm side output.
// Block: 256 threads, 32 rows x N cols. Each warp owns 4 rows (LN = warp reduce).
// Thread register tile: 4 rows x (N/32) cols.
// ---------------------------------------------------------------------------
template<int K, int N, bool LN, bool RELU, bool SQNORM>
__global__ void __launch_bounds__(256)
gemm_fused(const float* __restrict__ X, const float* __restrict__ W,
           const float* __restrict__ Bv, const float* __restrict__ Gv,
           const float* __restrict__ Be, float* __restrict__ Out,
           float* __restrict__ SqN)
{
    constexpr int MT = 32;
    constexpr int KT = 16;
    constexpr int G   = N / 128;   // float4 column groups per lane
    constexpr int CPT = N / 32;    // cols per thread = 4*G

    extern __shared__ float sm[];
    float* xs = sm;                // [MT][KT]
    float* ws = sm + MT * KT;      // [KT][N]

    const int tid  = threadIdx.x;
    const int lane = tid & 31;
    const int wid  = tid >> 5;
    const int row0 = blockIdx.x * MT;

    float acc[4][CPT];
#pragma unroll
    for (int j = 0; j < 4; ++j)
#pragma unroll
        for (int c = 0; c < CPT; ++c) acc[j][c] = 0.f;

    const int xi = tid >> 3;        // 0..31 (row within tile)
    const int xj = (tid & 7) * 2;   // 0..14 (k within chunk, float2)

    for (int kt = 0; kt < K; kt += KT) {
        // stage X tile [32][16]
        {
            float2 xv = *reinterpret_cast<const float2*>(&X[(size_t)(row0 + xi) * K + kt + xj]);
            xs[xi * KT + xj]     = xv.x;
            xs[xi * KT + xj + 1] = xv.y;
        }
        // stage W tile [16][N]
#pragma unroll
        for (int it = 0; it < (KT * N / 4) / 256; ++it) {
            int idx = tid + it * 256;
            int k   = idx / (N / 4);
            int c4  = idx % (N / 4);
            *reinterpret_cast<float4*>(&ws[k * N + c4 * 4]) =
                *reinterpret_cast<const float4*>(&W[(size_t)(kt + k) * N + c4 * 4]);
        }
        __syncthreads();

#pragma unroll
        for (int kk = 0; kk < KT; kk += 4) {
            float xq[4][4];
#pragma unroll
            for (int j = 0; j < 4; ++j) {
                float4 xr = *reinterpret_cast<const float4*>(&xs[(wid * 4 + j) * KT + kk]);
                xq[j][0] = xr.x; xq[j][1] = xr.y; xq[j][2] = xr.z; xq[j][3] = xr.w;
            }
#pragma unroll
            for (int q = 0; q < 4; ++q) {
#pragma unroll
                for (int g = 0; g < G; ++g) {
                    float4 w4 = *reinterpret_cast<const float4*>(
                        &ws[(kk + q) * N + g * 128 + lane * 4]);
                    float wv[4] = {w4.x, w4.y, w4.z, w4.w};
#pragma unroll
                    for (int j = 0; j < 4; ++j) {
#pragma unroll
                        for (int t = 0; t < 4; ++t)
                            acc[j][g * 4 + t] = fmaf(xq[j][q], wv[t], acc[j][g * 4 + t]);
                    }
                }
            }
        }
        __syncthreads();
    }

    // ---- epilogue ----
    float bbv[CPT];
#pragma unroll
    for (int g = 0; g < G; ++g) {
        float4 b4 = *reinterpret_cast<const float4*>(&Bv[g * 128 + lane * 4]);
        bbv[g * 4 + 0] = b4.x; bbv[g * 4 + 1] = b4.y;
        bbv[g * 4 + 2] = b4.z; bbv[g * 4 + 3] = b4.w;
    }
#pragma unroll
    for (int j = 0; j < 4; ++j)
#pragma unroll
        for (int c = 0; c < CPT; ++c) acc[j][c] += bbv[c];

    if constexpr (LN) {
        float ggv[CPT], eev[CPT];
#pragma unroll
        for (int g = 0; g < G; ++g) {
            float4 g4 = *reinterpret_cast<const float4*>(&Gv[g * 128 + lane * 4]);
            float4 e4 = *reinterpret_cast<const float4*>(&Be[g * 128 + lane * 4]);
            ggv[g * 4 + 0] = g4.x; ggv[g * 4 + 1] = g4.y; ggv[g * 4 + 2] = g4.z; ggv[g * 4 + 3] = g4.w;
            eev[g * 4 + 0] = e4.x; eev[g * 4 + 1] = e4.y; eev[g * 4 + 2] = e4.z; eev[g * 4 + 3] = e4.w;
        }
#pragma unroll
        for (int j = 0; j < 4; ++j) {
            float s = 0.f, sq = 0.f;
#pragma unroll
            for (int c = 0; c < CPT; ++c) { s += acc[j][c]; sq += acc[j][c] * acc[j][c]; }
#pragma unroll
            for (int off = 16; off > 0; off >>= 1) {
                s  += __shfl_xor_sync(0xFFFFFFFFu, s,  off);
                sq += __shfl_xor_sync(0xFFFFFFFFu, sq, off);
            }
            float mean = s * (1.f / N);
            float var  = sq * (1.f / N) - mean * mean;
            float rstd = rsqrtf(var + 1e-5f);
#pragma unroll
            for (int c = 0; c < CPT; ++c) {
                float v = (acc[j][c] - mean) * rstd * ggv[c] + eev[c];
                if (RELU) v = fmaxf(v, 0.f);
                acc[j][c] = v;
            }
        }
    } else if constexpr (RELU) {
#pragma unroll
        for (int j = 0; j < 4; ++j)
#pragma unroll
            for (int c = 0; c < CPT; ++c) acc[j][c] = fmaxf(acc[j][c], 0.f);
    }

#pragma unroll
    for (int j = 0; j < 4; ++j) {
        int row = row0 + wid * 4 + j;
#pragma unroll
        for (int g = 0; g < G; ++g) {
            float4 o;
            o.x = acc[j][g * 4 + 0]; o.y = acc[j][g * 4 + 1];
            o.z = acc[j][g * 4 + 2]; o.w = acc[j][g * 4 + 3];
            *reinterpret_cast<float4*>(&Out[(size_t)row * N + g * 128 + lane * 4]) = o;
        }
        if constexpr (SQNORM) {
            float s = 0.f;
#pragma unroll
            for (int c = 0; c < CPT; ++c) s += acc[j][c] * acc[j][c];
#pragma unroll
            for (int off = 16; off > 0; off >>= 1)
                s += __shfl_xor_sync(0xFFFFFFFFu, s, off);
            if (lane == 0) SqN[row] = s;
        }
    }
}

// ---------------------------------------------------------------------------
// Build distance GEMM operands: g_wd[k][p] = -2*protos[p][k] (pad p>=250 -> 0),
// g_bd[p] = ||proto_p||^2 (pad -> 1e30 so pads never enter top-k).
// One block per padded proto column, 128 threads over dims.
// ---------------------------------------------------------------------------
__global__ void prep_protos(const float* __restrict__ protos,
                            float* __restrict__ Wd, float* __restrict__ bd)
{
    int p = blockIdx.x;      // 0..255
    int d = threadIdx.x;     // 0..127
    float v = (p < 250) ? protos[p * 128 + d] : 0.f;
    Wd[d * 256 + p] = -2.f * v;
    float s = v * v;
#pragma unroll
    for (int off = 16; off > 0; off >>= 1)
        s += __shfl_xor_sync(0xFFFFFFFFu, s, off);
    __shared__ float ps[4];
    if ((d & 31) == 0) ps[d >> 5] = s;
    __syncthreads();
    if (d == 0) bd[p] = (p < 250) ? (ps[0] + ps[1] + ps[2] + ps[3]) : 1e30f;
}

// ---------------------------------------------------------------------------
// Top-15 + score. One warp per row over 256 padded distances.
// ---------------------------------------------------------------------------
__global__ void __launch_bounds__(256)
topk_kernel(const float* __restrict__ d2, const float* __restrict__ zz,
            float* __restrict__ out)
{
    int row  = blockIdx.x * 8 + (threadIdx.x >> 5);
    int lane = threadIdx.x & 31;
    float zzv = zz[row];
    float v[8];
    size_t base = (size_t)row * 256;
#pragma unroll
    for (int i = 0; i < 8; ++i)
        v[i] = sqrtf(fmaxf(d2[base + lane + 32 * i] + zzv, 0.f));

    float sum = 0.f, dmin = 0.f;
#pragma unroll
    for (int it = 0; it < KNN; ++it) {
        float mv = v[0]; int mi = lane;
#pragma unroll
        for (int i = 1; i < 8; ++i) {
            int idx = lane + 32 * i;
            if (v[i] < mv) { mv = v[i]; mi = idx; }
        }
#pragma unroll
        for (int off = 16; off > 0; off >>= 1) {
            float ov = __shfl_xor_sync(0xFFFFFFFFu, mv, off);
            int   oi = __shfl_xor_sync(0xFFFFFFFFu, mi, off);
            if (ov < mv || (ov == mv && oi < mi)) { mv = ov; mi = oi; }
        }
        if (it == 0) dmin = mv;
        sum += mv;
        if (lane == (mi & 31)) v[mi >> 5] = FLT_MAX;  // remove winner
    }
    if (lane == 0) {
        float lmre  = sum * (1.f / KNN);
        float score = 0.1f * lmre + 0.9f * dmin;
        out[row] = 1.f - expf(-0.3f * score);
    }
}

// ---------------------------------------------------------------------------
extern "C" void kernel_launch(void* const* d_in, const int* in_sizes, int n_in,
                              void* d_out, int out_size)
{
    const float* x      = (const float*)d_in[0];
    const float* w1     = (const float*)d_in[1];
    const float* b1     = (const float*)d_in[2];
    const float* g1     = (const float*)d_in[3];
    const float* be1    = (const float*)d_in[4];
    const float* w2     = (const float*)d_in[5];
    const float* b2     = (const float*)d_in[6];
    const float* g2     = (const float*)d_in[7];
    const float* be2    = (const float*)d_in[8];
    const float* w3     = (const float*)d_in[9];
    const float* b3     = (const float*)d_in[10];
    const float* protos = (const float*)d_in[11];
    float* out = (float*)d_out;

    void *p_h1, *p_h2, *p_z, *p_zz, *p_d2, *p_wd, *p_bd;
    cudaGetSymbolAddress(&p_h1, g_h1);
    cudaGetSymbolAddress(&p_h2, g_h2);
    cudaGetSymbolAddress(&p_z,  g_z);
    cudaGetSymbolAddress(&p_zz, g_zz);
    cudaGetSymbolAddress(&p_d2, g_d2);
    cudaGetSymbolAddress(&p_wd, g_wd);
    cudaGetSymbolAddress(&p_bd, g_bd);

    // distance operand prep (tiny)
    prep_protos<<<256, 128>>>(protos, (float*)p_wd, (float*)p_bd);

    constexpr int MT = 32, KT = 16;
    const int grid = NROWS / MT;

    // layer 1: [N,256] @ [256,512] + LN + ReLU
    gemm_fused<256, 512, true, true, false>
        <<<grid, 256, (MT * KT + KT * 512) * sizeof(float)>>>(
            x, w1, b1, g1, be1, (float*)p_h1, nullptr);

    // layer 2: [N,512] @ [512,256] + LN + ReLU
    gemm_fused<512, 256, true, true, false>
        <<<grid, 256, (MT * KT + KT * 256) * sizeof(float)>>>(
            (const float*)p_h1, w2, b2, g2, be2, (float*)p_h2, nullptr);

    // layer 3: [N,256] @ [256,128] + ReLU, emits ||z||^2
    gemm_fused<256, 128, false, true, true>
        <<<grid, 256, (MT * KT + KT * 128) * sizeof(float)>>>(
            (const float*)p_h2, w3, b3, nullptr, nullptr, (float*)p_z, (float*)p_zz);

    // distance: [N,128] @ [128,256] + ||p||^2 bias  (= d2 - zz)
    gemm_fused<128, 256, false, false, false>
        <<<grid, 256, (MT * KT + KT * 256) * sizeof(float)>>>(
            (const float*)p_z, (const float*)p_wd, (const float*)p_bd,
            nullptr, nullptr, (float*)p_d2, nullptr);

    // top-15 + score
    topk_kernel<<<NROWS / 8, 256>>>((const float*)p_d2, (const float*)p_zz, out);
}

// round 3
// speedup vs baseline: 1.8409x; 1.8409x over previous
#include <cuda_runtime.h>
#include <cuda_bf16.h>
#include <cfloat>
#include <math.h>
#include <cstdint>

#define NROWS 65536
#define KNN   15

// ---------------- scratch (device globals; no allocs allowed) ----------------
__device__ __nv_bfloat16 g_h1h[NROWS * 512], g_h1l[NROWS * 512];
__device__ __nv_bfloat16 g_h2h[NROWS * 256], g_h2l[NROWS * 256];
__device__ __nv_bfloat16 g_zh [NROWS * 128], g_zl [NROWS * 128];
__device__ __nv_bfloat16 g_w1h[256 * 512], g_w1l[256 * 512];   // [K=256][N=512]
__device__ __nv_bfloat16 g_w2h[512 * 256], g_w2l[512 * 256];   // [K=512][N=256]
__device__ __nv_bfloat16 g_w3h[256 * 128], g_w3l[256 * 128];   // [K=256][N=128]
__device__ __nv_bfloat16 g_wdh[128 * 256], g_wdl[128 * 256];   // [K=128][P=256] = -2*protos^T
__device__ float g_bd[256];          // ||proto||^2, pad = 1e30
__device__ float g_zz[NROWS];        // ||z||^2
__device__ float g_d2[NROWS * 256];  // z@(-2 p^T) + ||p||^2   (d2 - zz)

// ---------------- helpers ----------------
__device__ __forceinline__ uint32_t smem_u32(const void* p) {
    uint32_t a;
    asm("{ .reg .u64 t; cvta.to.shared.u64 t, %1; cvt.u32.u64 %0, t; }" : "=r"(a) : "l"(p));
    return a;
}
__device__ __forceinline__ void ldsm4(uint32_t* r, uint32_t addr) {
    asm volatile("ldmatrix.sync.aligned.m8n8.x4.shared.b16 {%0,%1,%2,%3}, [%4];"
                 : "=r"(r[0]), "=r"(r[1]), "=r"(r[2]), "=r"(r[3]) : "r"(addr));
}
__device__ __forceinline__ void ldsm4t(uint32_t* r, uint32_t addr) {
    asm volatile("ldmatrix.sync.aligned.m8n8.x4.trans.shared.b16 {%0,%1,%2,%3}, [%4];"
                 : "=r"(r[0]), "=r"(r[1]), "=r"(r[2]), "=r"(r[3]) : "r"(addr));
}
__device__ __forceinline__ void mma_bf16(float* d, const uint32_t* a, const uint32_t* b) {
    asm volatile(
        "mma.sync.aligned.m16n8k16.row.col.f32.bf16.bf16.f32 "
        "{%0,%1,%2,%3}, {%4,%5,%6,%7}, {%8,%9}, {%0,%1,%2,%3};"
        : "+f"(d[0]), "+f"(d[1]), "+f"(d[2]), "+f"(d[3])
        : "r"(a[0]), "r"(a[1]), "r"(a[2]), "r"(a[3]), "r"(b[0]), "r"(b[1]));
}
__device__ __forceinline__ void split_bf16(float v, uint32_t& h, uint32_t& l) {
    __nv_bfloat16 hb = __float2bfloat16_rn(v);
    float resid = v - __bfloat162float(hb);
    __nv_bfloat16 lb = __float2bfloat16_rn(resid);
    h = (uint32_t)__bfloat16_as_ushort(hb);
    l = (uint32_t)__bfloat16_as_ushort(lb);
}

// ---------------------------------------------------------------------------
// bf16 split-GEMM via mma.sync m16n8k16.
// Out[M,N] = epi( A[M,K] @ B[K,N] + bias ),  A = Ah+Al, B = Bh+Bl,
// product approx= AhBh + AhBl + AlBh  (fp32 accum).
// CTA: 64 rows x N cols, 256 threads = 4 row-strips(16) x 2 col-halves(N/2).
// MODE 0: LayerNorm+ReLU -> bf16 hi/lo out.  MODE 1: ReLU + SqN -> bf16 hi/lo.
// MODE 2: bias only -> fp32 out.  AF32: A is fp32, split while staging.
// ---------------------------------------------------------------------------
template<int K, int N, int MODE, bool AF32>
__global__ void __launch_bounds__(256, 1)
gemm_mma(const void* __restrict__ Ain_hi, const __nv_bfloat16* __restrict__ Ain_lo,
         const __nv_bfloat16* __restrict__ Bh, const __nv_bfloat16* __restrict__ Bl,
         const float* __restrict__ bias, const float* __restrict__ gamma,
         const float* __restrict__ beta,
         __nv_bfloat16* __restrict__ Oh, __nv_bfloat16* __restrict__ Ol,
         float* __restrict__ Of, float* __restrict__ SqN)
{
    constexpr int NW  = N / 2;           // cols per warp-column
    constexpr int NT  = NW / 8;          // 8-col mma tiles per warp
    constexpr int CHUNKS = K / 64;
    constexpr int UPR = N / 8;           // uint4 units per B row
    constexpr int SM_A_HI = 0;           // 64x64 bf16 = 8KB
    constexpr int SM_A_LO = 8192;
    constexpr int SM_B_HI = 16384;       // 64xN bf16 = 128*N bytes
    constexpr int SM_B_LO = 16384 + 128 * N;
    constexpr int SM_PAR  = 16384 + 256 * N;

    extern __shared__ char smem[];
    const uint32_t sb = smem_u32(smem);
    const int tid  = threadIdx.x;
    const int lane = tid & 31;
    const int wid  = tid >> 5;
    const int rg   = wid & 3;            // row strip
    const int ch   = wid >> 2;           // col half
    const int row0 = blockIdx.x * 64;

    // stage epilogue params to smem
    float* pr = (float*)(smem + SM_PAR);
    for (int i = tid; i < N; i += 256) {
        pr[i] = bias[i];
        if (MODE == 0) { pr[N + i] = gamma[i]; pr[2 * N + i] = beta[i]; }
    }

    float acc[NT][4];
#pragma unroll
    for (int t = 0; t < NT; ++t)
#pragma unroll
        for (int j = 0; j < 4; ++j) acc[t][j] = 0.f;

    for (int c = 0; c < CHUNKS; ++c) {
        const int kt = c * 64;
        __syncthreads();
        // ---- stage A [64 x 64] hi/lo, swizzled ----
        if constexpr (AF32) {
            const float* X = (const float*)Ain_hi;
#pragma unroll
            for (int it = 0; it < 4; ++it) {
                int idx = tid + it * 256;       // 0..1023
                int r = idx >> 4, u2 = idx & 15;
                float4 xv = ((const float4*)(X + (size_t)(row0 + r) * K + kt))[u2];
                uint32_t h0, l0, h1, l1, h2, l2, h3, l3;
                split_bf16(xv.x, h0, l0); split_bf16(xv.y, h1, l1);
                split_bf16(xv.z, h2, l2); split_bf16(xv.w, h3, l3);
                int du = r * 8 + ((u2 >> 1) ^ (r & 7));
                ((uint2*)(smem + SM_A_HI))[du * 2 + (u2 & 1)] =
                    make_uint2(h0 | (h1 << 16), h2 | (h3 << 16));
                ((uint2*)(smem + SM_A_LO))[du * 2 + (u2 & 1)] =
                    make_uint2(l0 | (l1 << 16), l2 | (l3 << 16));
            }
        } else {
            const __nv_bfloat16* Ah = (const __nv_bfloat16*)Ain_hi;
#pragma unroll
            for (int it = 0; it < 2; ++it) {
                int idx = tid + it * 256;       // 0..511
                int r = idx >> 3, u = idx & 7;
                int di = r * 8 + (u ^ (r & 7));
                ((uint4*)(smem + SM_A_HI))[di] =
                    ((const uint4*)(Ah + (size_t)(row0 + r) * K + kt))[u];
                ((uint4*)(smem + SM_A_LO))[di] =
                    ((const uint4*)(Ain_lo + (size_t)(row0 + r) * K + kt))[u];
            }
        }
        // ---- stage B [64 x N] hi/lo, swizzled (B gmem is [K][N] row-major) ----
#pragma unroll
        for (int it = 0; it < N / 32; ++it) {
            int idx = tid + it * 256;           // 0..8N-1 units
            int k = idx / UPR, u = idx % UPR;
            int di = k * UPR + (u ^ (k & 7));
            ((uint4*)(smem + SM_B_HI))[di] = ((const uint4*)(Bh + (size_t)(kt + k) * N))[u];
            ((uint4*)(smem + SM_B_LO))[di] = ((const uint4*)(Bl + (size_t)(kt + k) * N))[u];
        }
        __syncthreads();

        // ---- mma over 4 k-steps of 16 ----
#pragma unroll
        for (int kk4 = 0; kk4 < 4; ++kk4) {
            uint32_t ahi[4], alo[4];
            {
                int ar = rg * 16 + (lane & 15);
                uint32_t aoff = (uint32_t)((ar * 8 + (((kk4 * 2) + (lane >> 4)) ^ (ar & 7))) * 16);
                ldsm4(ahi, sb + SM_A_HI + aoff);
                ldsm4(alo, sb + SM_A_LO + aoff);
            }
            int bk = kk4 * 16 + (lane & 15);
#pragma unroll
            for (int nt2 = 0; nt2 < NT / 2; ++nt2) {
                int n0 = ch * NW + nt2 * 16;
                int bun = ((n0 >> 3) + (lane >> 4)) ^ (bk & 7);
                uint32_t boff = (uint32_t)((bk * UPR + bun) * 16);
                uint32_t bh[4], bl[4];
                ldsm4t(bh, sb + SM_B_HI + boff);
                ldsm4t(bl, sb + SM_B_LO + boff);
#pragma unroll
                for (int j = 0; j < 2; ++j) {
                    mma_bf16(acc[nt2 * 2 + j], ahi, bh + 2 * j);
                    mma_bf16(acc[nt2 * 2 + j], ahi, bl + 2 * j);
                    mma_bf16(acc[nt2 * 2 + j], alo, bh + 2 * j);
                }
            }
        }
    }

    __syncthreads();   // all mma done; smem A region reusable for reduction

    // ---- epilogue ----
    // fragment: d0,d1 -> row rA = rg*16 + (lane>>2), cols c,c+1
    //           d2,d3 -> row rB = rA + 8
    float* red = (float*)smem;   // [64 rows][2 ch][2 stats]
    const int q   = lane & 3;
    const int rin = lane >> 2;
    const int rowA = row0 + rg * 16 + rin;
    const int rowB = rowA + 8;

    if constexpr (MODE == 0) {
        float s0 = 0.f, q0 = 0.f, s1 = 0.f, q1 = 0.f;
#pragma unroll
        for (int nt = 0; nt < NT; ++nt) {
            int cc = ch * NW + nt * 8 + q * 2;
            float b0 = pr[cc], b1 = pr[cc + 1];
            acc[nt][0] += b0; acc[nt][1] += b1; acc[nt][2] += b0; acc[nt][3] += b1;
            s0 += acc[nt][0] + acc[nt][1]; q0 += acc[nt][0] * acc[nt][0] + acc[nt][1] * acc[nt][1];
            s1 += acc[nt][2] + acc[nt][3]; q1 += acc[nt][2] * acc[nt][2] + acc[nt][3] * acc[nt][3];
        }
#pragma unroll
        for (int off = 1; off <= 2; off <<= 1) {
            s0 += __shfl_xor_sync(0xFFFFFFFFu, s0, off);
            q0 += __shfl_xor_sync(0xFFFFFFFFu, q0, off);
            s1 += __shfl_xor_sync(0xFFFFFFFFu, s1, off);
            q1 += __shfl_xor_sync(0xFFFFFFFFu, q1, off);
        }
        if (q == 0) {
            int bA = ((rg * 16 + rin) * 2 + ch) * 2;
            int bB = ((rg * 16 + rin + 8) * 2 + ch) * 2;
            red[bA] = s0; red[bA + 1] = q0;
            red[bB] = s1; red[bB + 1] = q1;
        }
        __syncthreads();
        {
            int oA = ((rg * 16 + rin) * 2 + (ch ^ 1)) * 2;
            int oB = ((rg * 16 + rin + 8) * 2 + (ch ^ 1)) * 2;
            s0 += red[oA]; q0 += red[oA + 1];
            s1 += red[oB]; q1 += red[oB + 1];
        }
        float m0 = s0 * (1.f / N), r0s = rsqrtf(q0 * (1.f / N) - m0 * m0 + 1e-5f);
        float m1 = s1 * (1.f / N), r1s = rsqrtf(q1 * (1.f / N) - m1 * m1 + 1e-5f);
#pragma unroll
        for (int nt = 0; nt < NT; ++nt) {
            int cc = ch * NW + nt * 8 + q * 2;
            float g0 = pr[N + cc], g1 = pr[N + cc + 1];
            float e0 = pr[2 * N + cc], e1 = pr[2 * N + cc + 1];
            float v00 = fmaxf((acc[nt][0] - m0) * r0s * g0 + e0, 0.f);
            float v01 = fmaxf((acc[nt][1] - m0) * r0s * g1 + e1, 0.f);
            float v10 = fmaxf((acc[nt][2] - m1) * r1s * g0 + e0, 0.f);
            float v11 = fmaxf((acc[nt][3] - m1) * r1s * g1 + e1, 0.f);
            uint32_t h00, l00, h01, l01, h10, l10, h11, l11;
            split_bf16(v00, h00, l00); split_bf16(v01, h01, l01);
            split_bf16(v10, h10, l10); split_bf16(v11, h11, l11);
            *(uint32_t*)(Oh + (size_t)rowA * N + cc) = h00 | (h01 << 16);
            *(uint32_t*)(Ol + (size_t)rowA * N + cc) = l00 | (l01 << 16);
            *(uint32_t*)(Oh + (size_t)rowB * N + cc) = h10 | (h11 << 16);
            *(uint32_t*)(Ol + (size_t)rowB * N + cc) = l10 | (l11 << 16);
        }
    } else if constexpr (MODE == 1) {
        float q0 = 0.f, q1 = 0.f;
#pragma unroll
        for (int nt = 0; nt < NT; ++nt) {
            int cc = ch * NW + nt * 8 + q * 2;
            float b0 = pr[cc], b1 = pr[cc + 1];
            float v00 = fmaxf(acc[nt][0] + b0, 0.f);
            float v01 = fmaxf(acc[nt][1] + b1, 0.f);
            float v10 = fmaxf(acc[nt][2] + b0, 0.f);
            float v11 = fmaxf(acc[nt][3] + b1, 0.f);
            q0 += v00 * v00 + v01 * v01;
            q1 += v10 * v10 + v11 * v11;
            uint32_t h00, l00, h01, l01, h10, l10, h11, l11;
            split_bf16(v00, h00, l00); split_bf16(v01, h01, l01);
            split_bf16(v10, h10, l10); split_bf16(v11, h11, l11);
            *(uint32_t*)(Oh + (size_t)rowA * N + cc) = h00 | (h01 << 16);
            *(uint32_t*)(Ol + (size_t)rowA * N + cc) = l00 | (l01 << 16);
            *(uint32_t*)(Oh + (size_t)rowB * N + cc) = h10 | (h11 << 16);
            *(uint32_t*)(Ol + (size_t)rowB * N + cc) = l10 | (l11 << 16);
        }
#pragma unroll
        for (int off = 1; off <= 2; off <<= 1) {
            q0 += __shfl_xor_sync(0xFFFFFFFFu, q0, off);
            q1 += __shfl_xor_sync(0xFFFFFFFFu, q1, off);
        }
        if (q == 0) {
            red[((rg * 16 + rin) * 2 + ch) * 2] = q0;
            red[((rg * 16 + rin + 8) * 2 + ch) * 2] = q1;
        }
        __syncthreads();
        if (q == 0 && ch == 0) {
            SqN[rowA] = q0 + red[((rg * 16 + rin) * 2 + 1) * 2];
            SqN[rowB] = q1 + red[((rg * 16 + rin + 8) * 2 + 1) * 2];
        }
    } else {  // MODE 2
#pragma unroll
        for (int nt = 0; nt < NT; ++nt) {
            int cc = ch * NW + nt * 8 + q * 2;
            float b0 = pr[cc], b1 = pr[cc + 1];
            *(float2*)(Of + (size_t)rowA * N + cc) = make_float2(acc[nt][0] + b0, acc[nt][1] + b1);
            *(float2*)(Of + (size_t)rowB * N + cc) = make_float2(acc[nt][2] + b0, acc[nt][3] + b1);
        }
    }
}

// ---------------------------------------------------------------------------
// Weight prep: elementwise fp32 -> bf16 hi/lo split (layout preserved [K][N])
// ---------------------------------------------------------------------------
__global__ void wsplit(const float* __restrict__ W, __nv_bfloat16* __restrict__ Oh,
                       __nv_bfloat16* __restrict__ Ol, int total)
{
    int id = blockIdx.x * 256 + threadIdx.x;
    if (id >= total) return;
    float v = W[id];
    __nv_bfloat16 hb = __float2bfloat16_rn(v);
    Oh[id] = hb;
    Ol[id] = __float2bfloat16_rn(v - __bfloat162float(hb));
}

// protos [250,128] -> Wd [128][256] = split(-2*protos^T) (pad cols 0), bd = ||p||^2 (pad 1e30)
__global__ void proto_prep(const float* __restrict__ protos,
                           __nv_bfloat16* __restrict__ Oh, __nv_bfloat16* __restrict__ Ol,
                           float* __restrict__ bd)
{
    int p = blockIdx.x, d = threadIdx.x;
    float v = (p < 250) ? protos[p * 128 + d] : 0.f;
    float m2 = -2.f * v;
    __nv_bfloat16 hb = __float2bfloat16_rn(m2);
    Oh[d * 256 + p] = hb;
    Ol[d * 256 + p] = __float2bfloat16_rn(m2 - __bfloat162float(hb));
    float s = v * v;
#pragma unroll
    for (int off = 16; off > 0; off >>= 1)
        s += __shfl_xor_sync(0xFFFFFFFFu, s, off);
    __shared__ float ps[4];
    if ((d & 31) == 0) ps[d >> 5] = s;
    __syncthreads();
    if (d == 0) bd[p] = (p < 250) ? (ps[0] + ps[1] + ps[2] + ps[3]) : 1e30f;
}

// ---------------------------------------------------------------------------
// Top-15 + score. One warp per row over 256 padded distances.
// ---------------------------------------------------------------------------
__global__ void __launch_bounds__(256)
topk_kernel(const float* __restrict__ d2, const float* __restrict__ zz,
            float* __restrict__ out)
{
    int row  = blockIdx.x * 8 + (threadIdx.x >> 5);
    int lane = threadIdx.x & 31;
    float zzv = zz[row];
    float v[8];
    size_t base = (size_t)row * 256;
#pragma unroll
    for (int i = 0; i < 8; ++i)
        v[i] = sqrtf(fmaxf(d2[base + lane + 32 * i] + zzv, 0.f));

    float sum = 0.f, dmin = 0.f;
#pragma unroll
    for (int it = 0; it < KNN; ++it) {
        float mv = v[0]; int mi = lane;
#pragma unroll
        for (int i = 1; i < 8; ++i) {
            int idx = lane + 32 * i;
            if (v[i] < mv) { mv = v[i]; mi = idx; }
        }
#pragma unroll
        for (int off = 16; off > 0; off >>= 1) {
            float ov = __shfl_xor_sync(0xFFFFFFFFu, mv, off);
            int   oi = __shfl_xor_sync(0xFFFFFFFFu, mi, off);
            if (ov < mv || (ov == mv && oi < mi)) { mv = ov; mi = oi; }
        }
        if (it == 0) dmin = mv;
        sum += mv;
        if (lane == (mi & 31)) v[mi >> 5] = FLT_MAX;
    }
    if (lane == 0) {
        float lmre  = sum * (1.f / KNN);
        float score = 0.1f * lmre + 0.9f * dmin;
        out[row] = 1.f - expf(-0.3f * score);
    }
}

// ---------------------------------------------------------------------------
extern "C" void kernel_launch(void* const* d_in, const int* in_sizes, int n_in,
                              void* d_out, int out_size)
{
    const float* x      = (const float*)d_in[0];
    const float* w1     = (const float*)d_in[1];
    const float* b1     = (const float*)d_in[2];
    const float* g1     = (const float*)d_in[3];
    const float* be1    = (const float*)d_in[4];
    const float* w2     = (const float*)d_in[5];
    const float* b2     = (const float*)d_in[6];
    const float* g2     = (const float*)d_in[7];
    const float* be2    = (const float*)d_in[8];
    const float* w3     = (const float*)d_in[9];
    const float* b3     = (const float*)d_in[10];
    const float* protos = (const float*)d_in[11];
    float* out = (float*)d_out;

    void *p_h1h, *p_h1l, *p_h2h, *p_h2l, *p_zh, *p_zl;
    void *p_w1h, *p_w1l, *p_w2h, *p_w2l, *p_w3h, *p_w3l, *p_wdh, *p_wdl;
    void *p_bd, *p_zz, *p_d2;
    cudaGetSymbolAddress(&p_h1h, g_h1h); cudaGetSymbolAddress(&p_h1l, g_h1l);
    cudaGetSymbolAddress(&p_h2h, g_h2h); cudaGetSymbolAddress(&p_h2l, g_h2l);
    cudaGetSymbolAddress(&p_zh,  g_zh);  cudaGetSymbolAddress(&p_zl,  g_zl);
    cudaGetSymbolAddress(&p_w1h, g_w1h); cudaGetSymbolAddress(&p_w1l, g_w1l);
    cudaGetSymbolAddress(&p_w2h, g_w2h); cudaGetSymbolAddress(&p_w2l, g_w2l);
    cudaGetSymbolAddress(&p_w3h, g_w3h); cudaGetSymbolAddress(&p_w3l, g_w3l);
    cudaGetSymbolAddress(&p_wdh, g_wdh); cudaGetSymbolAddress(&p_wdl, g_wdl);
    cudaGetSymbolAddress(&p_bd,  g_bd);  cudaGetSymbolAddress(&p_zz,  g_zz);
    cudaGetSymbolAddress(&p_d2,  g_d2);

    // smem: 16384 (A) + 256*N (B hi/lo) + 12*N (params)
    constexpr int SMEM_N512 = 16384 + 256 * 512 + 12 * 512;   // 153600
    constexpr int SMEM_N256 = 16384 + 256 * 256 + 12 * 256;   // 84992
    constexpr int SMEM_N128 = 16384 + 256 * 128 + 12 * 128;   // 50688

    auto kL1 = gemm_mma<256, 512, 0, true>;
    auto kL2 = gemm_mma<512, 256, 0, false>;
    auto kL3 = gemm_mma<256, 128, 1, false>;
    auto kLD = gemm_mma<128, 256, 2, false>;
    cudaFuncSetAttribute(kL1, cudaFuncAttributeMaxDynamicSharedMemorySize, SMEM_N512);
    cudaFuncSetAttribute(kL2, cudaFuncAttributeMaxDynamicSharedMemorySize, SMEM_N256);
    cudaFuncSetAttribute(kL3, cudaFuncAttributeMaxDynamicSharedMemorySize, SMEM_N128);
    cudaFuncSetAttribute(kLD, cudaFuncAttributeMaxDynamicSharedMemorySize, SMEM_N256);

    // weight prep (tiny)
    wsplit<<<(256 * 512 + 255) / 256, 256>>>(w1, (__nv_bfloat16*)p_w1h, (__nv_bfloat16*)p_w1l, 256 * 512);
    wsplit<<<(512 * 256 + 255) / 256, 256>>>(w2, (__nv_bfloat16*)p_w2h, (__nv_bfloat16*)p_w2l, 512 * 256);
    wsplit<<<(256 * 128 + 255) / 256, 256>>>(w3, (__nv_bfloat16*)p_w3h, (__nv_bfloat16*)p_w3l, 256 * 128);
    proto_prep<<<256, 128>>>(protos, (__nv_bfloat16*)p_wdh, (__nv_bfloat16*)p_wdl, (float*)p_bd);

    const int grid = NROWS / 64;   // 1024

    kL1<<<grid, 256, SMEM_N512>>>(x, nullptr,
        (const __nv_bfloat16*)p_w1h, (const __nv_bfloat16*)p_w1l,
        b1, g1, be1,
        (__nv_bfloat16*)p_h1h, (__nv_bfloat16*)p_h1l, nullptr, nullptr);

    kL2<<<grid, 256, SMEM_N256>>>(p_h1h, (const __nv_bfloat16*)p_h1l,
        (const __nv_bfloat16*)p_w2h, (const __nv_bfloat16*)p_w2l,
        b2, g2, be2,
        (__nv_bfloat16*)p_h2h, (__nv_bfloat16*)p_h2l, nullptr, nullptr);

    kL3<<<grid, 256, SMEM_N128>>>(p_h2h, (const __nv_bfloat16*)p_h2l,
        (const __nv_bfloat16*)p_w3h, (const __nv_bfloat16*)p_w3l,
        b3, nullptr, nullptr,
        (__nv_bfloat16*)p_zh, (__nv_bfloat16*)p_zl, nullptr, (float*)p_zz);

    kLD<<<grid, 256, SMEM_N256>>>(p_zh, (const __nv_bfloat16*)p_zl,
        (const __nv_bfloat16*)p_wdh, (const __nv_bfloat16*)p_wdl,
        (const float*)p_bd, nullptr, nullptr,
        nullptr, nullptr, (float*)p_d2, nullptr);

    topk_kernel<<<NROWS / 8, 256>>>((const float*)p_d2, (const float*)p_zz, out);
}

// round 4
// speedup vs baseline: 1.9755x; 1.0731x over previous
#include <cuda_runtime.h>
#include <cuda_bf16.h>
#include <cfloat>
#include <math.h>
#include <cstdint>

#define NROWS 65536
#define KNN   15

// ---------------- scratch (device globals; no allocs allowed) ----------------
__device__ __nv_bfloat16 g_xh [NROWS * 256], g_xl [NROWS * 256];
__device__ __nv_bfloat16 g_h1h[NROWS * 512], g_h1l[NROWS * 512];
__device__ __nv_bfloat16 g_h2h[NROWS * 256], g_h2l[NROWS * 256];
__device__ __nv_bfloat16 g_w1h[256 * 512], g_w1l[256 * 512];   // [K][N]
__device__ __nv_bfloat16 g_w2h[512 * 256], g_w2l[512 * 256];
__device__ __nv_bfloat16 g_w3h[256 * 128], g_w3l[256 * 128];
__device__ __nv_bfloat16 g_wdh[128 * 256], g_wdl[128 * 256];   // [K=128][P=256] = -2*protos^T
__device__ float g_bd[256];   // ||proto||^2, pad = 1e30

// ---------------- helpers ----------------
__device__ __forceinline__ uint32_t smem_u32(const void* p) {
    uint32_t a;
    asm("{ .reg .u64 t; cvta.to.shared.u64 t, %1; cvt.u32.u64 %0, t; }" : "=r"(a) : "l"(p));
    return a;
}
__device__ __forceinline__ void ldsm4(uint32_t* r, uint32_t addr) {
    asm volatile("ldmatrix.sync.aligned.m8n8.x4.shared.b16 {%0,%1,%2,%3}, [%4];"
                 : "=r"(r[0]), "=r"(r[1]), "=r"(r[2]), "=r"(r[3]) : "r"(addr));
}
__device__ __forceinline__ void ldsm4t(uint32_t* r, uint32_t addr) {
    asm volatile("ldmatrix.sync.aligned.m8n8.x4.trans.shared.b16 {%0,%1,%2,%3}, [%4];"
                 : "=r"(r[0]), "=r"(r[1]), "=r"(r[2]), "=r"(r[3]) : "r"(addr));
}
__device__ __forceinline__ void mma_bf16(float* d, const uint32_t* a, const uint32_t* b) {
    asm volatile(
        "mma.sync.aligned.m16n8k16.row.col.f32.bf16.bf16.f32 "
        "{%0,%1,%2,%3}, {%4,%5,%6,%7}, {%8,%9}, {%0,%1,%2,%3};"
        : "+f"(d[0]), "+f"(d[1]), "+f"(d[2]), "+f"(d[3])
        : "r"(a[0]), "r"(a[1]), "r"(a[2]), "r"(a[3]), "r"(b[0]), "r"(b[1]));
}
__device__ __forceinline__ void cp16(uint32_t dst, const void* src) {
    asm volatile("cp.async.cg.shared.global [%0], [%1], 16;" :: "r"(dst), "l"(src));
}
__device__ __forceinline__ void cp_commit() { asm volatile("cp.async.commit_group;" ::: "memory"); }
template<int n> __device__ __forceinline__ void cp_wait() {
    asm volatile("cp.async.wait_group %0;" :: "n"(n) : "memory");
}
__device__ __forceinline__ void split_bf16(float v, uint32_t& h, uint32_t& l) {
    __nv_bfloat16 hb = __float2bfloat16_rn(v);
    float resid = v - __bfloat162float(hb);
    __nv_bfloat16 lb = __float2bfloat16_rn(resid);
    h = (uint32_t)__bfloat16_as_ushort(hb);
    l = (uint32_t)__bfloat16_as_ushort(lb);
}

// ---------------------------------------------------------------------------
// Pipelined LN+ReLU GEMM: Out = relu(LN(A@B + bias)) in bf16 hi/lo split.
// A (bf16 hi/lo, [M][K]) x B (bf16 hi/lo, [K][N]); 3-pass compensated product.
// CTA: 64 rows, 256 threads = 4 row-strips(16) x 2 col-halves(N/2).
// cp.async double-buffered K-chunks of size KC.
// ---------------------------------------------------------------------------
template<int K, int N, int KC>
__global__ void __launch_bounds__(256, 1)
ln_gemm(const __nv_bfloat16* __restrict__ Ah, const __nv_bfloat16* __restrict__ Al,
        const __nv_bfloat16* __restrict__ Bh, const __nv_bfloat16* __restrict__ Bl,
        const float* __restrict__ bias, const float* __restrict__ gamma,
        const float* __restrict__ beta,
        __nv_bfloat16* __restrict__ Oh, __nv_bfloat16* __restrict__ Ol)
{
    constexpr int P      = KC / 8 + 1;         // padded A row stride (16B units)
    constexpr int ABUF   = 64 * P * 16;
    constexpr int UPR    = N / 8;              // 16B units per B row
    constexpr int BBUF   = KC * N * 2;
    constexpr int CHUNKS = K / KC;
    constexpr int NW = N / 2, NT = NW / 8;
    constexpr int SM_PAR = 0;
    constexpr int SM_RED = 3 * N * 4;
    constexpr int SM_A   = SM_RED + 1024;
    constexpr int SM_B   = SM_A + 4 * ABUF;

    extern __shared__ char smem[];
    const uint32_t sb = smem_u32(smem);
    const int tid = threadIdx.x, lane = tid & 31, wid = tid >> 5;
    const int rg = wid & 3, ch = wid >> 2;
    const int row0 = blockIdx.x * 64;

    float* pr = (float*)(smem + SM_PAR);
    for (int i = tid; i < N; i += 256) {
        pr[i] = bias[i]; pr[N + i] = gamma[i]; pr[2 * N + i] = beta[i];
    }

    auto stage = [&](int c, int s) {
        const size_t kt = (size_t)c * KC;
        constexpr int AUPR = KC / 8;
        const uint32_t abh = sb + SM_A + (uint32_t)(s * 2 + 0) * ABUF;
        const uint32_t abl = sb + SM_A + (uint32_t)(s * 2 + 1) * ABUF;
#pragma unroll
        for (int i = 0; i < (64 * AUPR) / 256; ++i) {
            int idx = tid + i * 256;
            int r = idx / AUPR, u = idx % AUPR;
            uint32_t d = (uint32_t)((r * P + u) * 16);
            cp16(abh + d, Ah + (size_t)(row0 + r) * K + kt + u * 8);
            cp16(abl + d, Al + (size_t)(row0 + r) * K + kt + u * 8);
        }
        const uint32_t bbh = sb + SM_B + (uint32_t)(s * 2 + 0) * BBUF;
        const uint32_t bbl = sb + SM_B + (uint32_t)(s * 2 + 1) * BBUF;
#pragma unroll
        for (int i = 0; i < (KC * UPR) / 256; ++i) {
            int idx = tid + i * 256;
            int k = idx / UPR, u = idx % UPR;
            uint32_t d = (uint32_t)((k * UPR + (u ^ (k & 7))) * 16);
            cp16(bbh + d, Bh + (size_t)(kt + k) * N + u * 8);
            cp16(bbl + d, Bl + (size_t)(kt + k) * N + u * 8);
        }
    };

    float acc[NT][4];
#pragma unroll
    for (int t = 0; t < NT; ++t)
#pragma unroll
        for (int j = 0; j < 4; ++j) acc[t][j] = 0.f;

    stage(0, 0);
    cp_commit();

    for (int c = 0; c < CHUNKS; ++c) {
        if (c + 1 < CHUNKS) stage(c + 1, (c + 1) & 1);
        cp_commit();
        cp_wait<1>();
        __syncthreads();

        const uint32_t ahb = sb + SM_A + (uint32_t)((c & 1) * 2) * ABUF;
        const uint32_t alb = ahb + ABUF;
        const uint32_t bhb = sb + SM_B + (uint32_t)((c & 1) * 2) * BBUF;
        const uint32_t blb = bhb + BBUF;

#pragma unroll
        for (int kk = 0; kk < KC / 16; ++kk) {
            uint32_t afh[4], afl[4];
            int ar = rg * 16 + (lane & 15);
            int unit = kk * 2 + (lane >> 4);
            uint32_t aoff = (uint32_t)((ar * P + unit) * 16);
            ldsm4(afh, ahb + aoff);
            ldsm4(afl, alb + aoff);
            int bk = kk * 16 + (lane & 15);
#pragma unroll
            for (int nt2 = 0; nt2 < NT / 2; ++nt2) {
                int n0 = ch * NW + nt2 * 16;
                int bun = ((n0 >> 3) + (lane >> 4)) ^ (bk & 7);
                uint32_t boff = (uint32_t)((bk * UPR + bun) * 16);
                uint32_t bh[4], bl[4];
                ldsm4t(bh, bhb + boff);
                ldsm4t(bl, blb + boff);
#pragma unroll
                for (int j = 0; j < 2; ++j) {
                    mma_bf16(acc[nt2 * 2 + j], afh, bh + 2 * j);
                    mma_bf16(acc[nt2 * 2 + j], afh, bl + 2 * j);
                    mma_bf16(acc[nt2 * 2 + j], afl, bh + 2 * j);
                }
            }
        }
        __syncthreads();
    }

    // ---- LayerNorm + ReLU epilogue -> bf16 hi/lo ----
    float* red = (float*)(smem + SM_RED);
    const int q = lane & 3, rin = lane >> 2;
    const int rowA = row0 + rg * 16 + rin, rowB = rowA + 8;

    float s0 = 0.f, q0 = 0.f, s1 = 0.f, q1 = 0.f;
#pragma unroll
    for (int nt = 0; nt < NT; ++nt) {
        int cc = ch * NW + nt * 8 + q * 2;
        float b0 = pr[cc], b1 = pr[cc + 1];
        acc[nt][0] += b0; acc[nt][1] += b1; acc[nt][2] += b0; acc[nt][3] += b1;
        s0 += acc[nt][0] + acc[nt][1]; q0 += acc[nt][0] * acc[nt][0] + acc[nt][1] * acc[nt][1];
        s1 += acc[nt][2] + acc[nt][3]; q1 += acc[nt][2] * acc[nt][2] + acc[nt][3] * acc[nt][3];
    }
#pragma unroll
    for (int off = 1; off <= 2; off <<= 1) {
        s0 += __shfl_xor_sync(0xFFFFFFFFu, s0, off);
        q0 += __shfl_xor_sync(0xFFFFFFFFu, q0, off);
        s1 += __shfl_xor_sync(0xFFFFFFFFu, s1, off);
        q1 += __shfl_xor_sync(0xFFFFFFFFu, q1, off);
    }
    if (q == 0) {
        int bA = ((rg * 16 + rin) * 2 + ch) * 2;
        int bB = ((rg * 16 + rin + 8) * 2 + ch) * 2;
        red[bA] = s0; red[bA + 1] = q0;
        red[bB] = s1; red[bB + 1] = q1;
    }
    __syncthreads();
    {
        int oA = ((rg * 16 + rin) * 2 + (ch ^ 1)) * 2;
        int oB = ((rg * 16 + rin + 8) * 2 + (ch ^ 1)) * 2;
        s0 += red[oA]; q0 += red[oA + 1];
        s1 += red[oB]; q1 += red[oB + 1];
    }
    float m0 = s0 * (1.f / N), r0s = rsqrtf(q0 * (1.f / N) - m0 * m0 + 1e-5f);
    float m1 = s1 * (1.f / N), r1s = rsqrtf(q1 * (1.f / N) - m1 * m1 + 1e-5f);
#pragma unroll
    for (int nt = 0; nt < NT; ++nt) {
        int cc = ch * NW + nt * 8 + q * 2;
        float g0 = pr[N + cc], g1 = pr[N + cc + 1];
        float e0 = pr[2 * N + cc], e1 = pr[2 * N + cc + 1];
        float v00 = fmaxf((acc[nt][0] - m0) * r0s * g0 + e0, 0.f);
        float v01 = fmaxf((acc[nt][1] - m0) * r0s * g1 + e1, 0.f);
        float v10 = fmaxf((acc[nt][2] - m1) * r1s * g0 + e0, 0.f);
        float v11 = fmaxf((acc[nt][3] - m1) * r1s * g1 + e1, 0.f);
        uint32_t h00, l00, h01, l01, h10, l10, h11, l11;
        split_bf16(v00, h00, l00); split_bf16(v01, h01, l01);
        split_bf16(v10, h10, l10); split_bf16(v11, h11, l11);
        *(uint32_t*)(Oh + (size_t)rowA * N + cc) = h00 | (h01 << 16);
        *(uint32_t*)(Ol + (size_t)rowA * N + cc) = l00 | (l01 << 16);
        *(uint32_t*)(Oh + (size_t)rowB * N + cc) = h10 | (h11 << 16);
        *(uint32_t*)(Ol + (size_t)rowB * N + cc) = l10 | (l11 << 16);
    }
}

// ---------------------------------------------------------------------------
// Tail kernel: layer3 GEMM (h2@w3 + b3, ReLU) -> z in smem -> distance GEMM
// (z@wd + bd + zz) -> sqrt -> top-15 + score. One CTA = 64 rows.
// ---------------------------------------------------------------------------
__global__ void __launch_bounds__(256, 1)
tail_kernel(const __nv_bfloat16* __restrict__ Ah, const __nv_bfloat16* __restrict__ Al,
            const __nv_bfloat16* __restrict__ W3h, const __nv_bfloat16* __restrict__ W3l,
            const float* __restrict__ b3,
            const __nv_bfloat16* __restrict__ Wdh, const __nv_bfloat16* __restrict__ Wdl,
            const float* __restrict__ bd, float* __restrict__ out)
{
    // Phase A geometry: K=256, N=128, KC=64
    constexpr int KA = 256, NA = 128, KC = 64;
    constexpr int P = 9, ABUF = 64 * P * 16;          // 9216
    constexpr int UPR_A = NA / 8;                     // 16
    constexpr int BBUF = KC * NA * 2;                 // 16384
    constexpr int CHUNKS_A = KA / KC;                 // 4
    constexpr int NWA = 64, NTA = 8;
    // smem map
    constexpr int SM_ZZ  = 0;                         // 64 floats
    constexpr int SM_BD  = 256;                       // 256 floats
    constexpr int SM_B3  = 1280;                      // 128 floats
    constexpr int SM_RED = 2048;                      // 128 floats
    constexpr int SM_Z   = 4096;                      // z hi: 2*9216, lo: +18432
    constexpr int SM_S2  = 4096 + 36864;              // 40960, size 131072

    extern __shared__ char smem[];
    const uint32_t sb = smem_u32(smem);
    const int tid = threadIdx.x, lane = tid & 31, wid = tid >> 5;
    const int rg = wid & 3, ch = wid >> 2;
    const int row0 = blockIdx.x * 64;

    float* zzs = (float*)(smem + SM_ZZ);
    float* bds = (float*)(smem + SM_BD);
    float* b3s = (float*)(smem + SM_B3);
    float* red = (float*)(smem + SM_RED);
    bds[tid & 255] = bd[tid & 255];
    if (tid < 128) b3s[tid] = b3[tid];

    // ---- Phase A: h2 @ w3, pipelined ----
    auto stageA = [&](int c, int s) {
        const size_t kt = (size_t)c * KC;
        const uint32_t abh = sb + SM_S2 + (uint32_t)(s * 2 + 0) * ABUF;
        const uint32_t abl = sb + SM_S2 + (uint32_t)(s * 2 + 1) * ABUF;
#pragma unroll
        for (int i = 0; i < 2; ++i) {                 // 64 rows x 8 units / 256
            int idx = tid + i * 256;
            int r = idx >> 3, u = idx & 7;
            uint32_t d = (uint32_t)((r * P + u) * 16);
            cp16(abh + d, Ah + (size_t)(row0 + r) * KA + kt + u * 8);
            cp16(abl + d, Al + (size_t)(row0 + r) * KA + kt + u * 8);
        }
        const uint32_t bbh = sb + SM_S2 + 4 * ABUF + (uint32_t)(s * 2 + 0) * BBUF;
        const uint32_t bbl = sb + SM_S2 + 4 * ABUF + (uint32_t)(s * 2 + 1) * BBUF;
#pragma unroll
        for (int i = 0; i < 4; ++i) {                 // 64 k-rows x 16 units / 256
            int idx = tid + i * 256;
            int k = idx >> 4, u = idx & 15;
            uint32_t d = (uint32_t)((k * UPR_A + (u ^ (k & 7))) * 16);
            cp16(bbh + d, W3h + (size_t)(kt + k) * NA + u * 8);
            cp16(bbl + d, W3l + (size_t)(kt + k) * NA + u * 8);
        }
    };

    float acc[NTA][4];
#pragma unroll
    for (int t = 0; t < NTA; ++t)
#pragma unroll
        for (int j = 0; j < 4; ++j) acc[t][j] = 0.f;

    stageA(0, 0);
    cp_commit();
    for (int c = 0; c < CHUNKS_A; ++c) {
        if (c + 1 < CHUNKS_A) stageA(c + 1, (c + 1) & 1);
        cp_commit();
        cp_wait<1>();
        __syncthreads();
        const uint32_t ahb = sb + SM_S2 + (uint32_t)((c & 1) * 2) * ABUF;
        const uint32_t alb = ahb + ABUF;
        const uint32_t bhb = sb + SM_S2 + 4 * ABUF + (uint32_t)((c & 1) * 2) * BBUF;
        const uint32_t blb = bhb + BBUF;
#pragma unroll
        for (int kk = 0; kk < KC / 16; ++kk) {
            uint32_t afh[4], afl[4];
            int ar = rg * 16 + (lane & 15);
            int unit = kk * 2 + (lane >> 4);
            uint32_t aoff = (uint32_t)((ar * P + unit) * 16);
            ldsm4(afh, ahb + aoff);
            ldsm4(afl, alb + aoff);
            int bk = kk * 16 + (lane & 15);
#pragma unroll
            for (int nt2 = 0; nt2 < NTA / 2; ++nt2) {
                int n0 = ch * NWA + nt2 * 16;
                int bun = ((n0 >> 3) + (lane >> 4)) ^ (bk & 7);
                uint32_t boff = (uint32_t)((bk * UPR_A + bun) * 16);
                uint32_t bh[4], bl[4];
                ldsm4t(bh, bhb + boff);
                ldsm4t(bl, blb + boff);
#pragma unroll
                for (int j = 0; j < 2; ++j) {
                    mma_bf16(acc[nt2 * 2 + j], afh, bh + 2 * j);
                    mma_bf16(acc[nt2 * 2 + j], afh, bl + 2 * j);
                    mma_bf16(acc[nt2 * 2 + j], afl, bh + 2 * j);
                }
            }
        }
        __syncthreads();
    }

    // ---- stage wd into S2 (overlaps with z epilogue below) ----
    {
        const uint32_t wh = sb + SM_S2;              // 2 chunks x 32768
        const uint32_t wl = sb + SM_S2 + 65536;
#pragma unroll
        for (int i = 0; i < 16; ++i) {               // 128 rows x 32 units / 256
            int idx = tid + i * 256;
            int k = idx >> 5, u = idx & 31;
            int chk = k >> 6, kc = k & 63;
            uint32_t d = (uint32_t)(chk * 32768 + (kc * 32 + (u ^ (kc & 7))) * 16);
            cp16(wh + d, Wdh + (size_t)k * 256 + u * 8);
            cp16(wl + d, Wdl + (size_t)k * 256 + u * 8);
        }
        cp_commit();
    }

    // ---- z epilogue: bias + ReLU, sqnorm, split into smem z tile ----
    const int q = lane & 3, rin = lane >> 2;
    const int rlA = rg * 16 + rin, rlB = rlA + 8;
    float q0 = 0.f, q1 = 0.f;
#pragma unroll
    for (int nt = 0; nt < NTA; ++nt) {
        int cc = ch * 64 + nt * 8 + q * 2;
        float b0 = b3s[cc], b1 = b3s[cc + 1];
        float v00 = fmaxf(acc[nt][0] + b0, 0.f);
        float v01 = fmaxf(acc[nt][1] + b1, 0.f);
        float v10 = fmaxf(acc[nt][2] + b0, 0.f);
        float v11 = fmaxf(acc[nt][3] + b1, 0.f);
        q0 += v00 * v00 + v01 * v01;
        q1 += v10 * v10 + v11 * v11;
        uint32_t h00, l00, h01, l01, h10, l10, h11, l11;
        split_bf16(v00, h00, l00); split_bf16(v01, h01, l01);
        split_bf16(v10, h10, l10); split_bf16(v11, h11, l11);
        // z tile layout: [chunk=ch][row][unit=nt], P=9, +q*4 bytes within unit
        uint32_t zA = (uint32_t)(SM_Z + ch * 9216 + (rlA * P + nt) * 16 + q * 4);
        uint32_t zB = (uint32_t)(SM_Z + ch * 9216 + (rlB * P + nt) * 16 + q * 4);
        *(uint32_t*)(smem + zA)         = h00 | (h01 << 16);
        *(uint32_t*)(smem + zA + 18432) = l00 | (l01 << 16);
        *(uint32_t*)(smem + zB)         = h10 | (h11 << 16);
        *(uint32_t*)(smem + zB + 18432) = l10 | (l11 << 16);
    }
#pragma unroll
    for (int off = 1; off <= 2; off <<= 1) {
        q0 += __shfl_xor_sync(0xFFFFFFFFu, q0, off);
        q1 += __shfl_xor_sync(0xFFFFFFFFu, q1, off);
    }
    if (q == 0) {
        red[rlA * 2 + ch] = q0;
        red[rlB * 2 + ch] = q1;
    }
    __syncthreads();
    if (tid < 64) zzs[tid] = red[tid * 2] + red[tid * 2 + 1];
    cp_wait<0>();
    __syncthreads();

    // ---- Phase B: z @ wd (K=128, N=256) ----
    constexpr int NTB = 16;
    float acc2[NTB][4];
#pragma unroll
    for (int t = 0; t < NTB; ++t)
#pragma unroll
        for (int j = 0; j < 4; ++j) acc2[t][j] = 0.f;

    for (int chk = 0; chk < 2; ++chk) {
#pragma unroll
        for (int kk = 0; kk < 4; ++kk) {
            uint32_t afh[4], afl[4];
            int ar = rg * 16 + (lane & 15);
            int unit = kk * 2 + (lane >> 4);
            uint32_t aoff = (uint32_t)(SM_Z + chk * 9216 + (ar * P + unit) * 16);
            ldsm4(afh, sb + aoff);
            ldsm4(afl, sb + aoff + 18432);
            int bk = kk * 16 + (lane & 15);
#pragma unroll
            for (int nt2 = 0; nt2 < NTB / 2; ++nt2) {
                int n0 = ch * 128 + nt2 * 16;
                int bun = ((n0 >> 3) + (lane >> 4)) ^ (bk & 7);
                uint32_t boff = (uint32_t)(SM_S2 + chk * 32768 + (bk * 32 + bun) * 16);
                uint32_t bh[4], bl[4];
                ldsm4t(bh, sb + boff);
                ldsm4t(bl, sb + boff + 65536);
#pragma unroll
                for (int j = 0; j < 2; ++j) {
                    mma_bf16(acc2[nt2 * 2 + j], afh, bh + 2 * j);
                    mma_bf16(acc2[nt2 * 2 + j], afh, bl + 2 * j);
                    mma_bf16(acc2[nt2 * 2 + j], afl, bh + 2 * j);
                }
            }
        }
    }
    __syncthreads();   // done reading wd; S2 becomes the d2 tile

    // ---- d = sqrt(d2) into smem ----
    float* d2s = (float*)(smem + SM_S2);
    {
        float zzA = zzs[rlA], zzB = zzs[rlB];
#pragma unroll
        for (int nt = 0; nt < NTB; ++nt) {
            int cc = ch * 128 + nt * 8 + q * 2;
            float c0 = bds[cc], c1 = bds[cc + 1];
            d2s[rlA * 258 + cc]     = sqrtf(fmaxf(acc2[nt][0] + c0 + zzA, 0.f));
            d2s[rlA * 258 + cc + 1] = sqrtf(fmaxf(acc2[nt][1] + c1 + zzA, 0.f));
            d2s[rlB * 258 + cc]     = sqrtf(fmaxf(acc2[nt][2] + c0 + zzB, 0.f));
            d2s[rlB * 258 + cc + 1] = sqrtf(fmaxf(acc2[nt][3] + c1 + zzB, 0.f));
        }
    }
    __syncthreads();

    // ---- top-15 + score; warp w handles rows w*8 .. w*8+7 ----
    for (int rr = 0; rr < 8; ++rr) {
        int rl = wid * 8 + rr;
        float v[8];
#pragma unroll
        for (int i = 0; i < 8; ++i) v[i] = d2s[rl * 258 + lane + 32 * i];
        float sum = 0.f, dmin = 0.f;
#pragma unroll
        for (int it = 0; it < KNN; ++it) {
            float mv = v[0]; int mi = lane;
#pragma unroll
            for (int i = 1; i < 8; ++i) {
                int idx = lane + 32 * i;
                if (v[i] < mv) { mv = v[i]; mi = idx; }
            }
#pragma unroll
            for (int off = 16; off > 0; off >>= 1) {
                float ov = __shfl_xor_sync(0xFFFFFFFFu, mv, off);
                int   oi = __shfl_xor_sync(0xFFFFFFFFu, mi, off);
                if (ov < mv || (ov == mv && oi < mi)) { mv = ov; mi = oi; }
            }
            if (it == 0) dmin = mv;
            sum += mv;
            if (lane == (mi & 31)) v[mi >> 5] = FLT_MAX;
        }
        if (lane == 0) {
            float score = 0.1f * (sum * (1.f / KNN)) + 0.9f * dmin;
            out[row0 + rl] = 1.f - expf(-0.3f * score);
        }
    }
}

// ---------------------------------------------------------------------------
// prep kernels
// ---------------------------------------------------------------------------
__global__ void presplit(const float* __restrict__ X, __nv_bfloat16* __restrict__ Oh,
                         __nv_bfloat16* __restrict__ Ol)
{
    int id = blockIdx.x * 256 + threadIdx.x;       // one float4 each
    float4 v = ((const float4*)X)[id];
    uint32_t h0, l0, h1, l1, h2, l2, h3, l3;
    split_bf16(v.x, h0, l0); split_bf16(v.y, h1, l1);
    split_bf16(v.z, h2, l2); split_bf16(v.w, h3, l3);
    ((uint2*)Oh)[id] = make_uint2(h0 | (h1 << 16), h2 | (h3 << 16));
    ((uint2*)Ol)[id] = make_uint2(l0 | (l1 << 16), l2 | (l3 << 16));
}

__global__ void wsplit(const float* __restrict__ W, __nv_bfloat16* __restrict__ Oh,
                       __nv_bfloat16* __restrict__ Ol, int total)
{
    int id = blockIdx.x * 256 + threadIdx.x;
    if (id >= total) return;
    float v = W[id];
    __nv_bfloat16 hb = __float2bfloat16_rn(v);
    Oh[id] = hb;
    Ol[id] = __float2bfloat16_rn(v - __bfloat162float(hb));
}

__global__ void proto_prep(const float* __restrict__ protos,
                           __nv_bfloat16* __restrict__ Oh, __nv_bfloat16* __restrict__ Ol,
                           float* __restrict__ bd)
{
    int p = blockIdx.x, d = threadIdx.x;
    float v = (p < 250) ? protos[p * 128 + d] : 0.f;
    float m2 = -2.f * v;
    __nv_bfloat16 hb = __float2bfloat16_rn(m2);
    Oh[d * 256 + p] = hb;
    Ol[d * 256 + p] = __float2bfloat16_rn(m2 - __bfloat162float(hb));
    float s = v * v;
#pragma unroll
    for (int off = 16; off > 0; off >>= 1)
        s += __shfl_xor_sync(0xFFFFFFFFu, s, off);
    __shared__ float ps[4];
    if ((d & 31) == 0) ps[d >> 5] = s;
    __syncthreads();
    if (d == 0) bd[p] = (p < 250) ? (ps[0] + ps[1] + ps[2] + ps[3]) : 1e30f;
}

// ---------------------------------------------------------------------------
extern "C" void kernel_launch(void* const* d_in, const int* in_sizes, int n_in,
                              void* d_out, int out_size)
{
    const float* x      = (const float*)d_in[0];
    const float* w1     = (const float*)d_in[1];
    const float* b1     = (const float*)d_in[2];
    const float* g1     = (const float*)d_in[3];
    const float* be1    = (const float*)d_in[4];
    const float* w2     = (const float*)d_in[5];
    const float* b2     = (const float*)d_in[6];
    const float* g2     = (const float*)d_in[7];
    const float* be2    = (const float*)d_in[8];
    const float* w3     = (const float*)d_in[9];
    const float* b3     = (const float*)d_in[10];
    const float* protos = (const float*)d_in[11];
    float* out = (float*)d_out;

    void *p_xh, *p_xl, *p_h1h, *p_h1l, *p_h2h, *p_h2l;
    void *p_w1h, *p_w1l, *p_w2h, *p_w2l, *p_w3h, *p_w3l, *p_wdh, *p_wdl, *p_bd;
    cudaGetSymbolAddress(&p_xh,  g_xh);  cudaGetSymbolAddress(&p_xl,  g_xl);
    cudaGetSymbolAddress(&p_h1h, g_h1h); cudaGetSymbolAddress(&p_h1l, g_h1l);
    cudaGetSymbolAddress(&p_h2h, g_h2h); cudaGetSymbolAddress(&p_h2l, g_h2l);
    cudaGetSymbolAddress(&p_w1h, g_w1h); cudaGetSymbolAddress(&p_w1l, g_w1l);
    cudaGetSymbolAddress(&p_w2h, g_w2h); cudaGetSymbolAddress(&p_w2l, g_w2l);
    cudaGetSymbolAddress(&p_w3h, g_w3h); cudaGetSymbolAddress(&p_w3l, g_w3l);
    cudaGetSymbolAddress(&p_wdh, g_wdh); cudaGetSymbolAddress(&p_wdl, g_wdl);
    cudaGetSymbolAddress(&p_bd,  g_bd);

    // smem sizes
    constexpr int SMEM_L1 = 3 * 512 * 4 + 1024 + 4 * (64 * 5 * 16) + 4 * (32 * 512 * 2); // 158720
    constexpr int SMEM_L2 = 3 * 256 * 4 + 1024 + 4 * (64 * 9 * 16) + 4 * (64 * 256 * 2); // 172032
    constexpr int SMEM_TL = 40960 + 131072;                                              // 172032

    auto kL1 = ln_gemm<256, 512, 32>;
    auto kL2 = ln_gemm<512, 256, 64>;
    cudaFuncSetAttribute(kL1, cudaFuncAttributeMaxDynamicSharedMemorySize, SMEM_L1);
    cudaFuncSetAttribute(kL2, cudaFuncAttributeMaxDynamicSharedMemorySize, SMEM_L2);
    cudaFuncSetAttribute(tail_kernel, cudaFuncAttributeMaxDynamicSharedMemorySize, SMEM_TL);

    // prep
    presplit<<<NROWS * 256 / 4 / 256, 256>>>(x, (__nv_bfloat16*)p_xh, (__nv_bfloat16*)p_xl);
    wsplit<<<(256 * 512 + 255) / 256, 256>>>(w1, (__nv_bfloat16*)p_w1h, (__nv_bfloat16*)p_w1l, 256 * 512);
    wsplit<<<(512 * 256 + 255) / 256, 256>>>(w2, (__nv_bfloat16*)p_w2h, (__nv_bfloat16*)p_w2l, 512 * 256);
    wsplit<<<(256 * 128 + 255) / 256, 256>>>(w3, (__nv_bfloat16*)p_w3h, (__nv_bfloat16*)p_w3l, 256 * 128);
    proto_prep<<<256, 128>>>(protos, (__nv_bfloat16*)p_wdh, (__nv_bfloat16*)p_wdl, (float*)p_bd);

    const int grid = NROWS / 64;   // 1024

    kL1<<<grid, 256, SMEM_L1>>>((const __nv_bfloat16*)p_xh, (const __nv_bfloat16*)p_xl,
        (const __nv_bfloat16*)p_w1h, (const __nv_bfloat16*)p_w1l,
        b1, g1, be1, (__nv_bfloat16*)p_h1h, (__nv_bfloat16*)p_h1l);

    kL2<<<grid, 256, SMEM_L2>>>((const __nv_bfloat16*)p_h1h, (const __nv_bfloat16*)p_h1l,
        (const __nv_bfloat16*)p_w2h, (const __nv_bfloat16*)p_w2l,
        b2, g2, be2, (__nv_bfloat16*)p_h2h, (__nv_bfloat16*)p_h2l);

    tail_kernel<<<grid, 256, SMEM_TL>>>((const __nv_bfloat16*)p_h2h, (const __nv_bfloat16*)p_h2l,
        (const __nv_bfloat16*)p_w3h, (const __nv_bfloat16*)p_w3l, b3,
        (const __nv_bfloat16*)p_wdh, (const __nv_bfloat16*)p_wdl,
        (const float*)p_bd, out);
}